// round 1
// baseline (speedup 1.0000x reference)
#include <cuda_runtime.h>
#include <math.h>

#define NN 80000
#define EE 1280000
#define DHID 64
#define DOUT_FINAL 40

// ---------------- scratch (static device globals; no allocs) ----------------
__device__ float g_buf0[(size_t)NN * DHID];       // h after layer 0
__device__ float g_buf1[(size_t)NN * DHID];       // h after layer 1
__device__ float g_aggr[(size_t)NN * DHID];       // per-layer aggregation
__device__ float g_out3[(size_t)NN * DOUT_FINAL]; // logits
__device__ int   g_deg[NN];
__device__ float g_deginv[NN];
__device__ float g_acc[2];                        // {sum(nll*m), sum(m)}

// ---------------- small utility kernels ----------------
__global__ void k_zero_init() {
    int i = blockIdx.x * blockDim.x + threadIdx.x;
    if (i < NN) g_deg[i] = 0;
    if (i < 2)  g_acc[i] = 0.f;
}

__global__ void k_count_deg(const int* __restrict__ dst) {
    int e = blockIdx.x * blockDim.x + threadIdx.x;
    if (e < EE) atomicAdd(&g_deg[dst[e]], 1);
}

__global__ void k_deginv() {
    int i = blockIdx.x * blockDim.x + threadIdx.x;
    if (i < NN) {
        int d = g_deg[i];
        g_deginv[i] = (d > 0) ? 1.f / (float)d : 0.f;
    }
}

__global__ void k_zero_aggr() {
    int i = blockIdx.x * blockDim.x + threadIdx.x;
    if (i < NN * DHID / 4) ((float4*)g_aggr)[i] = make_float4(0.f, 0.f, 0.f, 0.f);
}

// ---------------- edge scatter: aggr[dst] += h[src] ----------------
__device__ __forceinline__ void red_add_v4(float* addr, float4 v) {
    asm volatile("red.global.add.v4.f32 [%0], {%1, %2, %3, %4};"
                 :: "l"(addr), "f"(v.x), "f"(v.y), "f"(v.z), "f"(v.w)
                 : "memory");
}

__global__ void __launch_bounds__(256) k_scatter(const int* __restrict__ dst,
                                                 const int* __restrict__ src,
                                                 const float* __restrict__ hin) {
    int t = blockIdx.x * 256 + threadIdx.x;   // EE*16 = 20,480,000 threads
    if (t >= EE * 16) return;
    int e = t >> 4;
    int c = t & 15;
    int s = __ldg(src + e);
    int d = __ldg(dst + e);
    float4 v = __ldg((const float4*)(hin + (size_t)s * DHID) + c);
    red_add_v4(g_aggr + (size_t)d * DHID + (size_t)c * 4, v);
}

// ---------------- fused SAGE linear: out = act(aggr*deginv @ Wl^T + bl + h @ Wr^T + br)
// One GEMM: [64 nodes x 128] @ [128 x 64], K = concat(aggr_scaled, h),
// weights = stack(Wl^T, Wr^T) zero-padded to 64 output dims.
template<bool RELU>
__global__ void __launch_bounds__(128) k_transform(
    const float* __restrict__ hin,
    const float* __restrict__ Wl, const float* __restrict__ bl,
    const float* __restrict__ Wr, const float* __restrict__ br,
    float* __restrict__ out, int dout)
{
    extern __shared__ float sm[];
    float* s_in = sm;                 // [64][129]  (pad 129 -> conflict-free col reads)
    float* s_w  = sm + 64 * 129;      // [128][64]  s_w[k][d]
    float* s_b  = s_w + 128 * 64;     // [64]

    const int t  = threadIdx.x;       // 0..127
    const int nb = blockIdx.x * 64;   // NN = 1250 * 64 exactly

    // stage inputs: k<64 -> scaled aggregate, k>=64 -> h
    for (int i = t; i < 64 * 128; i += 128) {
        int n = i >> 7, k = i & 127;
        float v;
        if (k < 64) v = g_aggr[(size_t)(nb + n) * 64 + k] * g_deginv[nb + n];
        else        v = hin[(size_t)(nb + n) * 64 + (k - 64)];
        s_in[n * 129 + k] = v;
    }
    // stage weights transposed+stacked (pad d >= dout with zeros)
    for (int i = t; i < 128 * 64; i += 128) {
        int k = i >> 6, d = i & 63;
        float w = 0.f;
        if (d < dout) w = (k < 64) ? Wl[d * 64 + k] : Wr[d * 64 + (k - 64)];
        s_w[i] = w;
    }
    if (t < 64) s_b[t] = (t < dout) ? (bl[t] + br[t]) : 0.f;
    __syncthreads();

    const int nq = t & 15;   // node quad: nodes nq*4 .. nq*4+3
    const int dg = t >> 4;   // dim group: dims dg*8 .. dg*8+7

    float acc[4][8];
    #pragma unroll
    for (int j = 0; j < 4; ++j)
        #pragma unroll
        for (int dd = 0; dd < 8; ++dd) acc[j][dd] = s_b[dg * 8 + dd];

    const float4* w4 = (const float4*)s_w;
    #pragma unroll 4
    for (int k = 0; k < 128; ++k) {
        float4 w0 = w4[k * 16 + dg * 2];
        float4 w1 = w4[k * 16 + dg * 2 + 1];
        #pragma unroll
        for (int j = 0; j < 4; ++j) {
            float a = s_in[(nq * 4 + j) * 129 + k];
            acc[j][0] += a * w0.x; acc[j][1] += a * w0.y;
            acc[j][2] += a * w0.z; acc[j][3] += a * w0.w;
            acc[j][4] += a * w1.x; acc[j][5] += a * w1.y;
            acc[j][6] += a * w1.z; acc[j][7] += a * w1.w;
        }
    }

    #pragma unroll
    for (int j = 0; j < 4; ++j) {
        int n = nb + nq * 4 + j;
        #pragma unroll
        for (int dd = 0; dd < 8; ++dd) {
            int d = dg * 8 + dd;
            if (d < dout) {
                float v = acc[j][dd];
                if (RELU) v = fmaxf(v, 0.f);
                out[(size_t)n * dout + d] = v;
            }
        }
    }
}

// ---------------- loss: masked mean NLL of log_softmax ----------------
__global__ void k_loss(const int* __restrict__ y, const int* __restrict__ mask) {
    int i = blockIdx.x * blockDim.x + threadIdx.x;
    float nll = 0.f, m = 0.f;
    if (i < NN && mask[i] != 0) {
        const float* l = g_out3 + (size_t)i * DOUT_FINAL;
        float mx = l[0];
        #pragma unroll
        for (int d = 1; d < DOUT_FINAL; ++d) mx = fmaxf(mx, l[d]);
        float s = 0.f;
        #pragma unroll
        for (int d = 0; d < DOUT_FINAL; ++d) s += expf(l[d] - mx);
        nll = mx + logf(s) - l[y[i]];
        m = 1.f;
    }
    #pragma unroll
    for (int o = 16; o > 0; o >>= 1) {
        nll += __shfl_down_sync(0xffffffffu, nll, o);
        m   += __shfl_down_sync(0xffffffffu, m, o);
    }
    if ((threadIdx.x & 31) == 0) {
        atomicAdd(&g_acc[0], nll);
        atomicAdd(&g_acc[1], m);
    }
}

__global__ void k_final(float* out) {
    out[0] = g_acc[0] / fmaxf(g_acc[1], 1.f);
}

// ---------------- launcher ----------------
extern "C" void kernel_launch(void* const* d_in, const int* in_sizes, int n_in,
                              void* d_out, int out_size) {
    const float* x   = (const float*)d_in[0];
    const float* Wl0 = (const float*)d_in[1];
    const float* bl0 = (const float*)d_in[2];
    const float* Wr0 = (const float*)d_in[3];
    const float* br0 = (const float*)d_in[4];
    const float* Wl1 = (const float*)d_in[5];
    const float* bl1 = (const float*)d_in[6];
    const float* Wr1 = (const float*)d_in[7];
    const float* br1 = (const float*)d_in[8];
    const float* Wl2 = (const float*)d_in[9];
    const float* bl2 = (const float*)d_in[10];
    const float* Wr2 = (const float*)d_in[11];
    const float* br2 = (const float*)d_in[12];
    const int*   ei  = (const int*)d_in[13];
    const int*   y   = (const int*)d_in[14];
    const int*   msk = (const int*)d_in[15];
    const int* dst = ei;        // edge_index[0]
    const int* src = ei + EE;   // edge_index[1]

    float *buf0, *buf1, *out3;
    cudaGetSymbolAddress((void**)&buf0, g_buf0);
    cudaGetSymbolAddress((void**)&buf1, g_buf1);
    cudaGetSymbolAddress((void**)&out3, g_out3);

    const int smem = (64 * 129 + 128 * 64 + 64) * (int)sizeof(float); // 66304 B
    cudaFuncSetAttribute(k_transform<true>,  cudaFuncAttributeMaxDynamicSharedMemorySize, smem);
    cudaFuncSetAttribute(k_transform<false>, cudaFuncAttributeMaxDynamicSharedMemorySize, smem);

    k_zero_init<<<(NN + 255) / 256, 256>>>();
    k_count_deg<<<(EE + 255) / 256, 256>>>(dst);
    k_deginv<<<(NN + 255) / 256, 256>>>();

    const int scatter_blocks = (EE * 16) / 256;      // 80000
    const int zero_blocks    = (NN * DHID / 4) / 256; // 5000
    const int gemm_blocks    = NN / 64;               // 1250

    // layer 0: x -> buf0
    k_zero_aggr<<<zero_blocks, 256>>>();
    k_scatter<<<scatter_blocks, 256>>>(dst, src, x);
    k_transform<true><<<gemm_blocks, 128, smem>>>(x, Wl0, bl0, Wr0, br0, buf0, 64);

    // layer 1: buf0 -> buf1
    k_zero_aggr<<<zero_blocks, 256>>>();
    k_scatter<<<scatter_blocks, 256>>>(dst, src, buf0);
    k_transform<true><<<gemm_blocks, 128, smem>>>(buf0, Wl1, bl1, Wr1, br1, buf1, 64);

    // layer 2: buf1 -> out3 (40 dims, no relu)
    k_zero_aggr<<<zero_blocks, 256>>>();
    k_scatter<<<scatter_blocks, 256>>>(dst, src, buf1);
    k_transform<false><<<gemm_blocks, 128, smem>>>(buf1, Wl2, bl2, Wr2, br2, out3, 40);

    k_loss<<<(NN + 255) / 256, 256>>>(y, msk);
    k_final<<<1, 1>>>((float*)d_out);
}

// round 2
// speedup vs baseline: 1.2940x; 1.2940x over previous
#include <cuda_runtime.h>
#include <math.h>

#define NN 80000
#define EE 1280000
#define DHID 64
#define DOUT_FINAL 40
#define NB_SCAN 79   // ceil(80000/1024)

// ---------------- scratch (static device globals; no allocs) ----------------
__device__ float g_buf0[(size_t)NN * DHID];       // h after layer 0
__device__ float g_buf1[(size_t)NN * DHID];       // h after layer 1
__device__ float g_aggr[(size_t)NN * DHID];       // per-layer aggregation (pre-scaled)
__device__ float g_out3[(size_t)NN * DOUT_FINAL]; // logits
__device__ int   g_deg[NN];
__device__ float g_deginv[NN];
__device__ int   g_rowstart[NN + 1];
__device__ int   g_cursor[NN];
__device__ int   g_bsum[NB_SCAN];
__device__ int   g_csr[EE];                       // src indices grouped by dst
__device__ float g_acc[2];                        // {sum(nll*m), sum(m)}

// ---------------- CSR build ----------------
__global__ void k_zero_init() {
    int i = blockIdx.x * blockDim.x + threadIdx.x;
    if (i < NN) g_deg[i] = 0;
    if (i < 2)  g_acc[i] = 0.f;
}

__global__ void k_count_deg(const int* __restrict__ dst) {
    int e = blockIdx.x * blockDim.x + threadIdx.x;
    if (e < EE) atomicAdd(&g_deg[dst[e]], 1);
}

// per-chunk exclusive scan (chunk = 1024)
__global__ void __launch_bounds__(1024) k_scan1() {
    __shared__ int s[1024];
    int t = threadIdx.x;
    int i = blockIdx.x * 1024 + t;
    int v = (i < NN) ? g_deg[i] : 0;
    s[t] = v;
    __syncthreads();
    #pragma unroll
    for (int o = 1; o < 1024; o <<= 1) {
        int u = (t >= o) ? s[t - o] : 0;
        __syncthreads();
        s[t] += u;
        __syncthreads();
    }
    if (i < NN) g_rowstart[i] = s[t] - v;        // exclusive, chunk-local
    if (t == 1023) g_bsum[blockIdx.x] = s[t];
}

__global__ void k_scan2() {
    if (threadIdx.x == 0) {
        int acc = 0;
        for (int b = 0; b < NB_SCAN; ++b) {
            int v = g_bsum[b];
            g_bsum[b] = acc;
            acc += v;
        }
    }
}

__global__ void k_scan3() {
    int i = blockIdx.x * blockDim.x + threadIdx.x;
    if (i < NN) {
        int rs = g_rowstart[i] + g_bsum[i >> 10];
        g_rowstart[i] = rs;
        g_cursor[i]   = rs;
        int d = g_deg[i];
        g_deginv[i] = (d > 0) ? 1.f / (float)d : 0.f;
    }
    if (i == 0) g_rowstart[NN] = EE;
}

__global__ void k_build(const int* __restrict__ dst, const int* __restrict__ src) {
    int e = blockIdx.x * blockDim.x + threadIdx.x;
    if (e < EE) {
        int d = dst[e];
        int slot = atomicAdd(&g_cursor[d], 1);
        g_csr[slot] = src[e];
    }
}

// ---------------- warp-per-node CSR gather: aggr[n] = deginv[n] * sum h[nbr] ----
__global__ void __launch_bounds__(256) k_gather(const float* __restrict__ hin) {
    int warp = (blockIdx.x * 256 + threadIdx.x) >> 5;
    if (warp >= NN) return;
    int lane = threadIdx.x & 31;
    int half = lane >> 4;       // which neighbor of the pair
    int c    = lane & 15;       // float4 chunk within 64-float row
    int s0 = __ldg(g_rowstart + warp);
    int s1 = __ldg(g_rowstart + warp + 1);
    float4 acc = make_float4(0.f, 0.f, 0.f, 0.f);
    for (int j = s0 + half; j < s1; j += 2) {
        int s = __ldg(g_csr + j);
        float4 v = __ldg((const float4*)(hin + (size_t)s * DHID) + c);
        acc.x += v.x; acc.y += v.y; acc.z += v.z; acc.w += v.w;
    }
    // fold the two half-warps together
    acc.x += __shfl_down_sync(0xffffffffu, acc.x, 16);
    acc.y += __shfl_down_sync(0xffffffffu, acc.y, 16);
    acc.z += __shfl_down_sync(0xffffffffu, acc.z, 16);
    acc.w += __shfl_down_sync(0xffffffffu, acc.w, 16);
    if (half == 0) {
        float di = g_deginv[warp];
        acc.x *= di; acc.y *= di; acc.z *= di; acc.w *= di;
        ((float4*)(g_aggr + (size_t)warp * DHID))[c] = acc;
    }
}

// ---------------- fused SAGE linear: out = act(aggr @ Wl^T + bl + h @ Wr^T + br)
// One GEMM: [64 nodes x 128] @ [128 x 64], K = concat(aggr, h),
// weights = stack(Wl^T, Wr^T) zero-padded to 64 output dims.
template<bool RELU>
__global__ void __launch_bounds__(128) k_transform(
    const float* __restrict__ hin,
    const float* __restrict__ Wl, const float* __restrict__ bl,
    const float* __restrict__ Wr, const float* __restrict__ br,
    float* __restrict__ out, int dout)
{
    extern __shared__ float sm[];
    float* s_in = sm;                 // [64][129]
    float* s_w  = sm + 64 * 129;      // [128][64]
    float* s_b  = s_w + 128 * 64;     // [64]

    const int t  = threadIdx.x;
    const int nb = blockIdx.x * 64;   // NN = 1250 * 64

    for (int i = t; i < 64 * 128; i += 128) {
        int n = i >> 7, k = i & 127;
        float v = (k < 64) ? g_aggr[(size_t)(nb + n) * 64 + k]
                           : hin[(size_t)(nb + n) * 64 + (k - 64)];
        s_in[n * 129 + k] = v;
    }
    for (int i = t; i < 128 * 64; i += 128) {
        int k = i >> 6, d = i & 63;
        float w = 0.f;
        if (d < dout) w = (k < 64) ? Wl[d * 64 + k] : Wr[d * 64 + (k - 64)];
        s_w[i] = w;
    }
    if (t < 64) s_b[t] = (t < dout) ? (bl[t] + br[t]) : 0.f;
    __syncthreads();

    const int nq = t & 15;
    const int dg = t >> 4;

    float acc[4][8];
    #pragma unroll
    for (int j = 0; j < 4; ++j)
        #pragma unroll
        for (int dd = 0; dd < 8; ++dd) acc[j][dd] = s_b[dg * 8 + dd];

    const float4* w4 = (const float4*)s_w;
    #pragma unroll 4
    for (int k = 0; k < 128; ++k) {
        float4 w0 = w4[k * 16 + dg * 2];
        float4 w1 = w4[k * 16 + dg * 2 + 1];
        #pragma unroll
        for (int j = 0; j < 4; ++j) {
            float a = s_in[(nq * 4 + j) * 129 + k];
            acc[j][0] += a * w0.x; acc[j][1] += a * w0.y;
            acc[j][2] += a * w0.z; acc[j][3] += a * w0.w;
            acc[j][4] += a * w1.x; acc[j][5] += a * w1.y;
            acc[j][6] += a * w1.z; acc[j][7] += a * w1.w;
        }
    }

    #pragma unroll
    for (int j = 0; j < 4; ++j) {
        int n = nb + nq * 4 + j;
        #pragma unroll
        for (int dd = 0; dd < 8; ++dd) {
            int d = dg * 8 + dd;
            if (d < dout) {
                float v = acc[j][dd];
                if (RELU) v = fmaxf(v, 0.f);
                out[(size_t)n * dout + d] = v;
            }
        }
    }
}

// ---------------- loss: masked mean NLL of log_softmax ----------------
__global__ void k_loss(const int* __restrict__ y, const int* __restrict__ mask) {
    int i = blockIdx.x * blockDim.x + threadIdx.x;
    float nll = 0.f, m = 0.f;
    if (i < NN && mask[i] != 0) {
        const float* l = g_out3 + (size_t)i * DOUT_FINAL;
        float mx = l[0];
        #pragma unroll
        for (int d = 1; d < DOUT_FINAL; ++d) mx = fmaxf(mx, l[d]);
        float s = 0.f;
        #pragma unroll
        for (int d = 0; d < DOUT_FINAL; ++d) s += expf(l[d] - mx);
        nll = mx + logf(s) - l[y[i]];
        m = 1.f;
    }
    #pragma unroll
    for (int o = 16; o > 0; o >>= 1) {
        nll += __shfl_down_sync(0xffffffffu, nll, o);
        m   += __shfl_down_sync(0xffffffffu, m, o);
    }
    if ((threadIdx.x & 31) == 0) {
        atomicAdd(&g_acc[0], nll);
        atomicAdd(&g_acc[1], m);
    }
}

__global__ void k_final(float* out) {
    out[0] = g_acc[0] / fmaxf(g_acc[1], 1.f);
}

// ---------------- launcher ----------------
extern "C" void kernel_launch(void* const* d_in, const int* in_sizes, int n_in,
                              void* d_out, int out_size) {
    const float* x   = (const float*)d_in[0];
    const float* Wl0 = (const float*)d_in[1];
    const float* bl0 = (const float*)d_in[2];
    const float* Wr0 = (const float*)d_in[3];
    const float* br0 = (const float*)d_in[4];
    const float* Wl1 = (const float*)d_in[5];
    const float* bl1 = (const float*)d_in[6];
    const float* Wr1 = (const float*)d_in[7];
    const float* br1 = (const float*)d_in[8];
    const float* Wl2 = (const float*)d_in[9];
    const float* bl2 = (const float*)d_in[10];
    const float* Wr2 = (const float*)d_in[11];
    const float* br2 = (const float*)d_in[12];
    const int*   ei  = (const int*)d_in[13];
    const int*   y   = (const int*)d_in[14];
    const int*   msk = (const int*)d_in[15];
    const int* dst = ei;        // edge_index[0]
    const int* src = ei + EE;   // edge_index[1]

    float *buf0, *buf1, *out3;
    cudaGetSymbolAddress((void**)&buf0, g_buf0);
    cudaGetSymbolAddress((void**)&buf1, g_buf1);
    cudaGetSymbolAddress((void**)&out3, g_out3);

    const int smem = (64 * 129 + 128 * 64 + 64) * (int)sizeof(float); // 66304 B
    cudaFuncSetAttribute(k_transform<true>,  cudaFuncAttributeMaxDynamicSharedMemorySize, smem);
    cudaFuncSetAttribute(k_transform<false>, cudaFuncAttributeMaxDynamicSharedMemorySize, smem);

    // CSR build
    k_zero_init<<<(NN + 255) / 256, 256>>>();
    k_count_deg<<<(EE + 255) / 256, 256>>>(dst);
    k_scan1<<<NB_SCAN, 1024>>>();
    k_scan2<<<1, 32>>>();
    k_scan3<<<(NN + 255) / 256, 256>>>();
    k_build<<<(EE + 255) / 256, 256>>>(dst, src);

    const int gather_blocks = (NN * 32 + 255) / 256; // warp per node
    const int gemm_blocks   = NN / 64;               // 1250

    // layer 0: x -> buf0
    k_gather<<<gather_blocks, 256>>>(x);
    k_transform<true><<<gemm_blocks, 128, smem>>>(x, Wl0, bl0, Wr0, br0, buf0, 64);

    // layer 1: buf0 -> buf1
    k_gather<<<gather_blocks, 256>>>(buf0);
    k_transform<true><<<gemm_blocks, 128, smem>>>(buf0, Wl1, bl1, Wr1, br1, buf1, 64);

    // layer 2: buf1 -> out3 (40 dims, no relu)
    k_gather<<<gather_blocks, 256>>>(buf1);
    k_transform<false><<<gemm_blocks, 128, smem>>>(buf1, Wl2, bl2, Wr2, br2, out3, 40);

    k_loss<<<(NN + 255) / 256, 256>>>(y, msk);
    k_final<<<1, 1>>>((float*)d_out);
}